// round 2
// baseline (speedup 1.0000x reference)
#include <cuda_runtime.h>
#include <math.h>

#define D     196
#define NCH   64
#define H     8
#define DH    64
#define INNER 512
#define MLP   784
#define SEQ   65

// ---- scratch (no allocations allowed) ----
__device__ float g_a[NCH * D];
__device__ float g_b1[NCH];
__device__ float g_xatt[SEQ * D];
__device__ float g_h[SEQ * D];
__device__ float g_qkv[SEQ * 3 * INNER];
__device__ float g_o[SEQ * INNER];
__device__ float g_x1[SEQ * D];
__device__ float g_h2[SEQ * D];
__device__ float g_gelu[SEQ * MLP];

// ---------------- conv + bn + relu + row-mean ----------------
__global__ void k_conv(const float* __restrict__ xpe, const float* __restrict__ ck,
                       const float* __restrict__ bng, const float* __restrict__ bnb,
                       const float* __restrict__ bnrm, const float* __restrict__ bnrv) {
    int ch = blockIdx.x;
    int t  = threadIdx.x;
    __shared__ float red[256];
    const float* row = xpe + ch * D;
    float k0 = ck[3], k1 = ck[4], k2 = ck[5];
    float inv = rsqrtf(bnrv[0] + 1e-5f);
    float gg = bng[0], bb = bnb[0], rm = bnrm[0];
    float v = 0.f;
    if (t < D) {
        float left  = (t > 0)     ? row[t - 1] : 0.f;
        float mid   = row[t];
        float right = (t < D - 1) ? row[t + 1] : 0.f;
        float conv  = k0 * left + k1 * mid + k2 * right;
        float bn    = (conv - rm) * inv * gg + bb;
        v = fmaxf(bn, 0.f);
        g_a[ch * D + t] = v;
    }
    red[t] = v;
    __syncthreads();
    for (int s = 128; s > 0; s >>= 1) {
        if (t < s) red[t] += red[t + s];
        __syncthreads();
    }
    if (t == 0) g_b1[ch] = red[0] * (1.f / (float)D);
}

// ---------------- sort-gating + FC + x_att build ----------------
__global__ void k_gate(const float* __restrict__ tokens,
                       const float* __restrict__ fc1, const float* __restrict__ fc2) {
    int t = threadIdx.x;  // 64 threads
    __shared__ float b1s[NCH], b2s[NCH], ts[12], cs[NCH];
    __shared__ int middle_s;
    float b1 = g_b1[t];
    b1s[t] = b1;
    __syncthreads();
    if (t == 0) {
        float mx = -1e30f, mn = 1e30f;
        int cnt_le = 0, any_pos = 0;
        for (int i = 0; i < NCH; i++) {
            float v = b1s[i];
            mx = fmaxf(mx, v); mn = fminf(mn, v);
            if (v <= 0.f) cnt_le++; else any_pos = 1;
        }
        int middle;
        if (mx < 0.f || mn > 0.f) middle = 32;
        else middle = any_pos ? cnt_le : 0;
        middle_s = middle;
    }
    __syncthreads();
    // stable rank (matches stable argsort)
    int rank = 0;
    for (int j = 0; j < NCH; j++) {
        float vj = b1s[j];
        if (vj < b1 || (vj == b1 && j < t)) rank++;
    }
    int middle = middle_s;
    float ls = (float)middle, le = (float)(NCH - middle);
    float b2;
    if (rank < middle) b2 = b1 - 1.f / (1.f + powf(ls, b1));
    else               b2 = b1 + 1.f / (1.f + powf(le, -b1));
    b2s[t] = b2;
    __syncthreads();
    if (t < 12) {
        float acc = 0.f;
        for (int i = 0; i < NCH; i++) acc += b2s[i] * fc1[i * 12 + t];
        ts[t] = fmaxf(acc, 0.f);
    }
    __syncthreads();
    float acc = 0.f;
    for (int j = 0; j < 12; j++) acc += ts[j] * fc2[j * NCH + t];
    cs[t] = 1.f / (1.f + expf(-acc));
    __syncthreads();
    for (int idx = t; idx < NCH * D; idx += NCH) {
        int ch = idx / D;
        g_xatt[idx] = g_a[idx] * cs[ch];
    }
    for (int s = t; s < D; s += NCH) g_xatt[NCH * D + s] = tokens[s];
}

// ---------------- layernorm (row-wise over D) ----------------
__global__ void k_ln(const float* __restrict__ in, float* __restrict__ out,
                     const float* __restrict__ gam, const float* __restrict__ bet) {
    int row = blockIdx.x;
    int t = threadIdx.x;  // 256
    __shared__ float red[256];
    __shared__ float mean_s, rstd_s;
    float v = (t < D) ? in[row * D + t] : 0.f;
    red[t] = v;
    __syncthreads();
    for (int s = 128; s > 0; s >>= 1) { if (t < s) red[t] += red[t + s]; __syncthreads(); }
    if (t == 0) mean_s = red[0] * (1.f / (float)D);
    __syncthreads();
    float m = mean_s;
    float d = (t < D) ? (v - m) : 0.f;
    red[t] = d * d;
    __syncthreads();
    for (int s = 128; s > 0; s >>= 1) { if (t < s) red[t] += red[t + s]; __syncthreads(); }
    if (t == 0) rstd_s = rsqrtf(red[0] * (1.f / (float)D) + 1e-5f);
    __syncthreads();
    if (t < D) out[row * D + t] = d * rstd_s * gam[t] + bet[t];
}

// ---------------- qkv = h @ w_qkv ----------------
__global__ void k_qkv(const float* __restrict__ wqkv) {
    int row = blockIdx.y;
    int col = blockIdx.x * 128 + threadIdx.x;  // 0..1535
    __shared__ float hrow[D];
    for (int i = threadIdx.x; i < D; i += 128) hrow[i] = g_h[row * D + i];
    __syncthreads();
    float acc = 0.f;
    #pragma unroll 4
    for (int s = 0; s < D; s++) acc += hrow[s] * wqkv[s * (3 * INNER) + col];
    g_qkv[row * (3 * INNER) + col] = acc;
}

// ---------------- attention: one block per (head, query) ----------------
__global__ void k_attn() {
    int h = blockIdx.x, i = blockIdx.y;
    int t = threadIdx.x;  // 128
    __shared__ float q[DH];
    __shared__ float p[SEQ];
    if (t < DH) q[t] = g_qkv[i * (3 * INNER) + h * DH + t];
    __syncthreads();
    if (t < SEQ) {
        const float* kr = g_qkv + t * (3 * INNER) + INNER + h * DH;
        float acc = 0.f;
        #pragma unroll
        for (int d = 0; d < DH; d++) acc += q[d] * kr[d];
        p[t] = acc * 0.125f;
    }
    __syncthreads();
    if (t == 0) {
        float mx = -1e30f;
        for (int j = 0; j < SEQ; j++) mx = fmaxf(mx, p[j]);
        float sum = 0.f;
        for (int j = 0; j < SEQ; j++) { p[j] = expf(p[j] - mx); sum += p[j]; }
        float inv = 1.f / sum;
        for (int j = 0; j < SEQ; j++) p[j] *= inv;
    }
    __syncthreads();
    if (t < DH) {
        float acc = 0.f;
        for (int j = 0; j < SEQ; j++)
            acc += p[j] * g_qkv[j * (3 * INNER) + 2 * INNER + h * DH + t];
        g_o[i * INNER + h * DH + t] = acc;
    }
}

// ---------------- out-proj + residual + gated branch ----------------
__global__ void k_proj(const float* __restrict__ wout, const float* __restrict__ bout,
                       const float* __restrict__ x) {
    int row = blockIdx.x;
    int t = threadIdx.x;  // 256
    __shared__ float orow[INNER];
    for (int i = t; i < INNER; i += 256) orow[i] = g_o[row * INNER + i];
    __syncthreads();
    if (t < D) {
        float acc = bout[t];
        #pragma unroll 4
        for (int k = 0; k < INNER; k++) acc += orow[k] * wout[k * D + t];
        g_x1[row * D + t] = acc + x[row * D + t] + g_xatt[row * D + t];
    }
}

// ---------------- ff1 + gelu ----------------
__global__ void k_ff1(const float* __restrict__ w1, const float* __restrict__ b1) {
    int row = blockIdx.y;
    int col = blockIdx.x * 256 + threadIdx.x;
    __shared__ float hrow[D];
    for (int i = threadIdx.x; i < D; i += 256) hrow[i] = g_h2[row * D + i];
    __syncthreads();
    if (col < MLP) {
        float acc = b1[col];
        #pragma unroll 4
        for (int s = 0; s < D; s++) acc += hrow[s] * w1[s * MLP + col];
        // exact GELU
        float gv = 0.5f * acc * (1.f + erff(acc * 0.70710678118654752f));
        g_gelu[row * MLP + col] = gv;
    }
}

// ---------------- ff2 + residual -> out ----------------
__global__ void k_ff2(const float* __restrict__ w2, const float* __restrict__ b2,
                      float* __restrict__ out) {
    int row = blockIdx.x;
    int t = threadIdx.x;  // 256
    __shared__ float grow[MLP];
    for (int i = t; i < MLP; i += 256) grow[i] = g_gelu[row * MLP + i];
    __syncthreads();
    if (t < D) {
        float acc = b2[t];
        #pragma unroll 4
        for (int s = 0; s < MLP; s++) acc += grow[s] * w2[s * D + t];
        out[row * D + t] = acc + g_x1[row * D + t];
    }
}

extern "C" void kernel_launch(void* const* d_in, const int* in_sizes, int n_in,
                              void* d_out, int out_size) {
    const float* x      = (const float*)d_in[0];
    const float* tokens = (const float*)d_in[1];
    const float* x_pe   = (const float*)d_in[2];
    const float* conv_k = (const float*)d_in[3];
    const float* bn_g   = (const float*)d_in[4];
    const float* bn_b   = (const float*)d_in[5];
    const float* bn_rm  = (const float*)d_in[6];
    const float* bn_rv  = (const float*)d_in[7];
    const float* fc_w1  = (const float*)d_in[8];
    const float* fc_w2  = (const float*)d_in[9];
    const float* ln1_g  = (const float*)d_in[10];
    const float* ln1_b  = (const float*)d_in[11];
    const float* ln2_g  = (const float*)d_in[12];
    const float* ln2_b  = (const float*)d_in[13];
    const float* w_qkv  = (const float*)d_in[14];
    const float* w_out  = (const float*)d_in[15];
    const float* b_out  = (const float*)d_in[16];
    const float* ff_w1  = (const float*)d_in[17];
    const float* ff_b1  = (const float*)d_in[18];
    const float* ff_w2  = (const float*)d_in[19];
    const float* ff_b2  = (const float*)d_in[20];
    float* out = (float*)d_out;

    float* d_h;   cudaGetSymbolAddress((void**)&d_h, g_h);
    float* d_h2;  cudaGetSymbolAddress((void**)&d_h2, g_h2);
    float* d_x1;  cudaGetSymbolAddress((void**)&d_x1, g_x1);

    k_conv<<<NCH, 256>>>(x_pe, conv_k, bn_g, bn_b, bn_rm, bn_rv);
    k_gate<<<1, NCH>>>(tokens, fc_w1, fc_w2);
    k_ln<<<SEQ, 256>>>(x, d_h, ln1_g, ln1_b);
    k_qkv<<<dim3(12, SEQ), 128>>>(w_qkv);
    k_attn<<<dim3(H, SEQ), 128>>>();
    k_proj<<<SEQ, 256>>>(w_out, b_out, x);
    k_ln<<<SEQ, 256>>>(d_x1, d_h2, ln2_g, ln2_b);
    k_ff1<<<dim3(4, SEQ), 256>>>(ff_w1, ff_b1);
    k_ff2<<<SEQ, 256>>>(ff_w2, ff_b2, out);
}

// round 4
// speedup vs baseline: 1.1197x; 1.1197x over previous
#include <cuda_runtime.h>
#include <math.h>

#define D     196
#define NCH   64
#define H     8
#define DH    64
#define INNER 512
#define QKV3  1536
#define MLP   784
#define SEQ   65

// ---- scratch (no allocations allowed) ----
__device__ float g_a[NCH * D];
__device__ float g_b1[NCH];
__device__ float g_xatt[SEQ * D];
__device__ float g_h[SEQ * D];
__device__ float g_qkv[SEQ * QKV3];
__device__ float g_o[SEQ * INNER];
__device__ float g_x1[SEQ * D];
__device__ float g_h2[SEQ * D];
__device__ float g_gelu[SEQ * MLP];

// ---------------- conv + bn + relu + row-mean ----------------
__global__ void k_conv(const float* __restrict__ xpe, const float* __restrict__ ck,
                       const float* __restrict__ bng, const float* __restrict__ bnb,
                       const float* __restrict__ bnrm, const float* __restrict__ bnrv) {
    int ch = blockIdx.x;
    int t  = threadIdx.x;
    __shared__ float red[256];
    const float* row = xpe + ch * D;
    float k0 = ck[3], k1 = ck[4], k2 = ck[5];
    float inv = rsqrtf(bnrv[0] + 1e-5f);
    float gg = bng[0], bb = bnb[0], rm = bnrm[0];
    float v = 0.f;
    if (t < D) {
        float left  = (t > 0)     ? row[t - 1] : 0.f;
        float mid   = row[t];
        float right = (t < D - 1) ? row[t + 1] : 0.f;
        float conv  = k0 * left + k1 * mid + k2 * right;
        float bn    = (conv - rm) * inv * gg + bb;
        v = fmaxf(bn, 0.f);
        g_a[ch * D + t] = v;
    }
    red[t] = v;
    __syncthreads();
    for (int s = 128; s > 0; s >>= 1) {
        if (t < s) red[t] += red[t + s];
        __syncthreads();
    }
    if (t == 0) g_b1[ch] = red[0] * (1.f / (float)D);
}

// ---------------- sort-gating + FC + x_att build ----------------
__global__ void k_gate(const float* __restrict__ tokens,
                       const float* __restrict__ fc1, const float* __restrict__ fc2) {
    int t = threadIdx.x;  // 64 threads
    __shared__ float b1s[NCH], b2s[NCH], ts[12], cs[NCH];
    __shared__ int middle_s;
    float b1 = g_b1[t];
    b1s[t] = b1;
    __syncthreads();
    if (t == 0) {
        float mx = -1e30f, mn = 1e30f;
        int cnt_le = 0, any_pos = 0;
        for (int i = 0; i < NCH; i++) {
            float v = b1s[i];
            mx = fmaxf(mx, v); mn = fminf(mn, v);
            if (v <= 0.f) cnt_le++; else any_pos = 1;
        }
        int middle;
        if (mx < 0.f || mn > 0.f) middle = 32;
        else middle = any_pos ? cnt_le : 0;
        middle_s = middle;
    }
    __syncthreads();
    // stable rank (matches stable argsort)
    int rank = 0;
    for (int j = 0; j < NCH; j++) {
        float vj = b1s[j];
        if (vj < b1 || (vj == b1 && j < t)) rank++;
    }
    int middle = middle_s;
    float ls = (float)middle, le = (float)(NCH - middle);
    float b2;
    if (rank < middle) b2 = b1 - 1.f / (1.f + powf(ls, b1));
    else               b2 = b1 + 1.f / (1.f + powf(le, -b1));
    b2s[t] = b2;
    __syncthreads();
    if (t < 12) {
        float acc = 0.f;
        for (int i = 0; i < NCH; i++) acc += b2s[i] * fc1[i * 12 + t];
        ts[t] = fmaxf(acc, 0.f);
    }
    __syncthreads();
    float acc = 0.f;
    for (int j = 0; j < 12; j++) acc += ts[j] * fc2[j * NCH + t];
    cs[t] = 1.f / (1.f + expf(-acc));
    __syncthreads();
    for (int idx = t; idx < NCH * D; idx += NCH) {
        int ch = idx / D;
        g_xatt[idx] = g_a[idx] * cs[ch];
    }
    for (int s = t; s < D; s += NCH) g_xatt[NCH * D + s] = tokens[s];
}

// ---------------- layernorm (row-wise over D) ----------------
__global__ void k_ln(const float* __restrict__ in, float* __restrict__ out,
                     const float* __restrict__ gam, const float* __restrict__ bet) {
    int row = blockIdx.x;
    int t = threadIdx.x;  // 256
    __shared__ float red[256];
    __shared__ float mean_s, rstd_s;
    float v = (t < D) ? in[row * D + t] : 0.f;
    red[t] = v;
    __syncthreads();
    for (int s = 128; s > 0; s >>= 1) { if (t < s) red[t] += red[t + s]; __syncthreads(); }
    if (t == 0) mean_s = red[0] * (1.f / (float)D);
    __syncthreads();
    float m = mean_s;
    float d = (t < D) ? (v - m) : 0.f;
    red[t] = d * d;
    __syncthreads();
    for (int s = 128; s > 0; s >>= 1) { if (t < s) red[t] += red[t + s]; __syncthreads(); }
    if (t == 0) rstd_s = rsqrtf(red[0] * (1.f / (float)D) + 1e-5f);
    __syncthreads();
    if (t < D) out[row * D + t] = d * rstd_s * gam[t] + bet[t];
}

// ---------------- qkv = h @ w_qkv : col-owner threads, 5 rows/block ----------------
__global__ void k_qkv(const float* __restrict__ wq) {
    int col = blockIdx.x * 128 + threadIdx.x;   // < 1536
    int r0  = blockIdx.y * 5;                   // 13 groups x 5 = 65
    __shared__ __align__(16) float hs[5 * D];
    for (int i = threadIdx.x; i < 5 * D; i += 128) hs[i] = g_h[r0 * D + i];
    __syncthreads();
    float acc[5] = {0.f, 0.f, 0.f, 0.f, 0.f};
    #pragma unroll 1
    for (int s4 = 0; s4 < 49; s4++) {
        int s = s4 * 4;
        float w0 = wq[(s + 0) * QKV3 + col];
        float w1 = wq[(s + 1) * QKV3 + col];
        float w2 = wq[(s + 2) * QKV3 + col];
        float w3 = wq[(s + 3) * QKV3 + col];
        #pragma unroll
        for (int r = 0; r < 5; r++) {
            float4 hv = *(const float4*)(hs + r * D + s);
            acc[r] += hv.x * w0 + hv.y * w1 + hv.z * w2 + hv.w * w3;
        }
    }
    #pragma unroll
    for (int r = 0; r < 5; r++) g_qkv[(r0 + r) * QKV3 + col] = acc[r];
}

// ---------------- attention: one block per (head, query), parallel softmax ----------------
__global__ void k_attn() {
    int h = blockIdx.x, i = blockIdx.y;
    int t = threadIdx.x;  // 128
    __shared__ float q[DH];
    __shared__ float p[SEQ];
    __shared__ float redm[4], reds[4];
    if (t < DH) q[t] = g_qkv[i * QKV3 + h * DH + t];
    __syncthreads();
    float sc = -1e30f;
    if (t < SEQ) {
        const float* kr = g_qkv + t * QKV3 + INNER + h * DH;
        float a0 = 0.f, a1 = 0.f, a2 = 0.f, a3 = 0.f;
        #pragma unroll
        for (int d = 0; d < DH; d += 4) {
            a0 += q[d + 0] * kr[d + 0];
            a1 += q[d + 1] * kr[d + 1];
            a2 += q[d + 2] * kr[d + 2];
            a3 += q[d + 3] * kr[d + 3];
        }
        sc = (a0 + a1 + a2 + a3) * 0.125f;
    }
    float m = sc;
    for (int o = 16; o > 0; o >>= 1) m = fmaxf(m, __shfl_xor_sync(0xffffffffu, m, o));
    if ((t & 31) == 0) redm[t >> 5] = m;
    __syncthreads();
    m = fmaxf(fmaxf(redm[0], redm[1]), fmaxf(redm[2], redm[3]));
    float e = (t < SEQ) ? expf(sc - m) : 0.f;
    float ssum = e;
    for (int o = 16; o > 0; o >>= 1) ssum += __shfl_xor_sync(0xffffffffu, ssum, o);
    if ((t & 31) == 0) reds[t >> 5] = ssum;
    __syncthreads();
    float inv = 1.f / (reds[0] + reds[1] + reds[2] + reds[3]);
    if (t < SEQ) p[t] = e * inv;
    __syncthreads();
    if (t < DH) {
        float acc = 0.f;
        #pragma unroll 1
        for (int j = 0; j < SEQ; j++)
            acc += p[j] * g_qkv[j * QKV3 + 2 * INNER + h * DH + t];
        g_o[i * INNER + h * DH + t] = acc;
    }
}

// ---------------- out-proj + residual + gated branch ----------------
__global__ void k_proj(const float* __restrict__ wout, const float* __restrict__ bout,
                       const float* __restrict__ x) {
    int col = blockIdx.x * 128 + threadIdx.x;   // < 196 (guard)
    int r0  = blockIdx.y * 5;
    __shared__ __align__(16) float os[5 * INNER];
    for (int i = threadIdx.x; i < 5 * INNER; i += 128) os[i] = g_o[r0 * INNER + i];
    __syncthreads();
    if (col >= D) return;
    float b = bout[col];
    float acc[5] = {0.f, 0.f, 0.f, 0.f, 0.f};
    #pragma unroll 1
    for (int s4 = 0; s4 < INNER / 4; s4++) {
        int s = s4 * 4;
        float w0 = wout[(s + 0) * D + col];
        float w1 = wout[(s + 1) * D + col];
        float w2 = wout[(s + 2) * D + col];
        float w3 = wout[(s + 3) * D + col];
        #pragma unroll
        for (int r = 0; r < 5; r++) {
            float4 ov = *(const float4*)(os + r * INNER + s);
            acc[r] += ov.x * w0 + ov.y * w1 + ov.z * w2 + ov.w * w3;
        }
    }
    #pragma unroll
    for (int r = 0; r < 5; r++) {
        int row = r0 + r;
        g_x1[row * D + col] = acc[r] + b + x[row * D + col] + g_xatt[row * D + col];
    }
}

// ---------------- ff1 + gelu ----------------
__global__ void k_ff1(const float* __restrict__ w1, const float* __restrict__ b1) {
    int col = blockIdx.x * 128 + threadIdx.x;   // < 784 (guard)
    int r0  = blockIdx.y * 5;
    __shared__ __align__(16) float hs[5 * D];
    for (int i = threadIdx.x; i < 5 * D; i += 128) hs[i] = g_h2[r0 * D + i];
    __syncthreads();
    if (col >= MLP) return;
    float b = b1[col];
    float acc[5] = {0.f, 0.f, 0.f, 0.f, 0.f};
    #pragma unroll 1
    for (int s4 = 0; s4 < 49; s4++) {
        int s = s4 * 4;
        float w0 = w1[(s + 0) * MLP + col];
        float wv1 = w1[(s + 1) * MLP + col];
        float w2 = w1[(s + 2) * MLP + col];
        float w3 = w1[(s + 3) * MLP + col];
        #pragma unroll
        for (int r = 0; r < 5; r++) {
            float4 hv = *(const float4*)(hs + r * D + s);
            acc[r] += hv.x * w0 + hv.y * wv1 + hv.z * w2 + hv.w * w3;
        }
    }
    #pragma unroll
    for (int r = 0; r < 5; r++) {
        float a = acc[r] + b;
        float gv = 0.5f * a * (1.f + erff(a * 0.70710678118654752f));
        g_gelu[(r0 + r) * MLP + col] = gv;
    }
}

// ---------------- ff2 + residual -> out ----------------
__global__ void k_ff2(const float* __restrict__ w2, const float* __restrict__ b2,
                      float* __restrict__ out) {
    int col = blockIdx.x * 128 + threadIdx.x;   // < 196 (guard)
    int r0  = blockIdx.y * 5;
    __shared__ __align__(16) float gs[5 * MLP];
    for (int i = threadIdx.x; i < 5 * MLP; i += 128) gs[i] = g_gelu[r0 * MLP + i];
    __syncthreads();
    if (col >= D) return;
    float b = b2[col];
    float acc[5] = {0.f, 0.f, 0.f, 0.f, 0.f};
    #pragma unroll 1
    for (int s4 = 0; s4 < MLP / 4; s4++) {
        int s = s4 * 4;
        float w0 = w2[(s + 0) * D + col];
        float w1 = w2[(s + 1) * D + col];
        float wv2 = w2[(s + 2) * D + col];
        float w3 = w2[(s + 3) * D + col];
        #pragma unroll
        for (int r = 0; r < 5; r++) {
            float4 gv = *(const float4*)(gs + r * MLP + s);
            acc[r] += gv.x * w0 + gv.y * w1 + gv.z * wv2 + gv.w * w3;
        }
    }
    #pragma unroll
    for (int r = 0; r < 5; r++) {
        int row = r0 + r;
        out[row * D + col] = acc[r] + b + g_x1[row * D + col];
    }
}

extern "C" void kernel_launch(void* const* d_in, const int* in_sizes, int n_in,
                              void* d_out, int out_size) {
    const float* x      = (const float*)d_in[0];
    const float* tokens = (const float*)d_in[1];
    const float* x_pe   = (const float*)d_in[2];
    const float* conv_k = (const float*)d_in[3];
    const float* bn_g   = (const float*)d_in[4];
    const float* bn_b   = (const float*)d_in[5];
    const float* bn_rm  = (const float*)d_in[6];
    const float* bn_rv  = (const float*)d_in[7];
    const float* fc_w1  = (const float*)d_in[8];
    const float* fc_w2  = (const float*)d_in[9];
    const float* ln1_g  = (const float*)d_in[10];
    const float* ln1_b  = (const float*)d_in[11];
    const float* ln2_g  = (const float*)d_in[12];
    const float* ln2_b  = (const float*)d_in[13];
    const float* w_qkv  = (const float*)d_in[14];
    const float* w_out  = (const float*)d_in[15];
    const float* b_out  = (const float*)d_in[16];
    const float* ff_w1  = (const float*)d_in[17];
    const float* ff_b1  = (const float*)d_in[18];
    const float* ff_w2  = (const float*)d_in[19];
    const float* ff_b2  = (const float*)d_in[20];
    float* out = (float*)d_out;

    float* d_h;   cudaGetSymbolAddress((void**)&d_h, g_h);
    float* d_h2;  cudaGetSymbolAddress((void**)&d_h2, g_h2);
    float* d_x1;  cudaGetSymbolAddress((void**)&d_x1, g_x1);

    k_conv<<<NCH, 256>>>(x_pe, conv_k, bn_g, bn_b, bn_rm, bn_rv);
    k_gate<<<1, NCH>>>(tokens, fc_w1, fc_w2);
    k_ln<<<SEQ, 256>>>(x, d_h, ln1_g, ln1_b);
    k_qkv<<<dim3(12, 13), 128>>>(w_qkv);
    k_attn<<<dim3(H, SEQ), 128>>>();
    k_proj<<<dim3(2, 13), 128>>>(w_out, b_out, x);
    k_ln<<<SEQ, 256>>>(d_x1, d_h2, ln2_g, ln2_b);
    k_ff1<<<dim3(7, 13), 128>>>(ff_w1, ff_b1);
    k_ff2<<<dim3(2, 13), 128>>>(ff_w2, ff_b2, out);
}

// round 5
// speedup vs baseline: 1.8442x; 1.6470x over previous
#include <cuda_runtime.h>
#include <math.h>

#define D     196
#define NCH   64
#define H     8
#define DH    64
#define INNER 512
#define QKV3  1536
#define MLP   784
#define SEQ   65

// ---- scratch (no allocations allowed) ----
__device__ float g_xatt[SEQ * D];
__device__ float g_qkv[SEQ * QKV3];
__device__ float g_o[SEQ * INNER];
__device__ float g_x1[SEQ * D];
__device__ float g_gelu[SEQ * MLP];

// ================= conv + bn + relu + mean + sort-gate + FC + x_att =================
// Single block, 1024 threads. Conv values are recomputed in phase 2 (cheap) so no
// 50KB smem staging is needed.
__global__ void k_convgate(const float* __restrict__ xpe, const float* __restrict__ ck,
                           const float* __restrict__ bng, const float* __restrict__ bnb,
                           const float* __restrict__ bnrm, const float* __restrict__ bnrv,
                           const float* __restrict__ tokens,
                           const float* __restrict__ fc1, const float* __restrict__ fc2) {
    __shared__ float b1s[NCH], b2s[NCH], ts[12], cs[NCH];
    __shared__ int middle_s;
    int t = threadIdx.x;           // 1024
    int w = t >> 5, lane = t & 31; // 32 warps
    float k0 = ck[3], k1 = ck[4], k2 = ck[5];
    float inv = rsqrtf(bnrv[0] + 1e-5f);
    float gg = bng[0], bb = bnb[0], rm = bnrm[0];

    // phase 1: per-channel mean of relu(bn(conv)). warp w does rows w and w+32.
    #pragma unroll
    for (int rep = 0; rep < 2; rep++) {
        int ch = w + rep * 32;
        const float* row = xpe + ch * D;
        float s = 0.f;
        for (int p = lane; p < D; p += 32) {
            float left  = (p > 0)     ? row[p - 1] : 0.f;
            float mid   = row[p];
            float right = (p < D - 1) ? row[p + 1] : 0.f;
            float conv  = k0 * left + k1 * mid + k2 * right;
            float bn    = (conv - rm) * inv * gg + bb;
            s += fmaxf(bn, 0.f);
        }
        for (int o = 16; o > 0; o >>= 1) s += __shfl_xor_sync(0xffffffffu, s, o);
        if (lane == 0) b1s[ch] = s * (1.f / (float)D);
    }
    __syncthreads();
    if (t == 0) {
        float mx = -1e30f, mn = 1e30f;
        int cnt_le = 0, any_pos = 0;
        for (int i = 0; i < NCH; i++) {
            float v = b1s[i];
            mx = fmaxf(mx, v); mn = fminf(mn, v);
            if (v <= 0.f) cnt_le++; else any_pos = 1;
        }
        int middle;
        if (mx < 0.f || mn > 0.f) middle = 32;
        else middle = any_pos ? cnt_le : 0;
        middle_s = middle;
    }
    __syncthreads();
    if (t < NCH) {
        float b1 = b1s[t];
        int rank = 0;
        for (int j = 0; j < NCH; j++) {
            float vj = b1s[j];
            if (vj < b1 || (vj == b1 && j < t)) rank++;
        }
        int middle = middle_s;
        float ls = (float)middle, le = (float)(NCH - middle);
        float b2;
        if (rank < middle) b2 = b1 - 1.f / (1.f + powf(ls, b1));
        else               b2 = b1 + 1.f / (1.f + powf(le, -b1));
        b2s[t] = b2;
    }
    __syncthreads();
    if (t < 12) {
        float acc = 0.f;
        for (int i = 0; i < NCH; i++) acc += b2s[i] * fc1[i * 12 + t];
        ts[t] = fmaxf(acc, 0.f);
    }
    __syncthreads();
    if (t < NCH) {
        float acc = 0.f;
        for (int j = 0; j < 12; j++) acc += ts[j] * fc2[j * NCH + t];
        cs[t] = 1.f / (1.f + expf(-acc));
    }
    __syncthreads();
    // phase 2: recompute conv, scale by gate, write x_att (+ tokens row)
    for (int idx = t; idx < NCH * D; idx += 1024) {
        int ch = idx / D, p = idx - ch * D;
        const float* row = xpe + ch * D;
        float left  = (p > 0)     ? row[p - 1] : 0.f;
        float mid   = row[p];
        float right = (p < D - 1) ? row[p + 1] : 0.f;
        float conv  = k0 * left + k1 * mid + k2 * right;
        float bn    = (conv - rm) * inv * gg + bb;
        g_xatt[idx] = fmaxf(bn, 0.f) * cs[ch];
    }
    for (int s = t; s < D; s += 1024) g_xatt[NCH * D + s] = tokens[s];
}

// ================= LN1 (in-block) + qkv GEMM, K split 4 ways =================
// grid (12, 13), 512 threads: kc = t>>7 in [0,4), cl = t&127; 5 rows per block.
__global__ void k_qkv(const float* __restrict__ x, const float* __restrict__ ln1g,
                      const float* __restrict__ ln1b, const float* __restrict__ wq) {
    __shared__ float hs[5 * D];
    __shared__ float sred[3 * 5 * 128];
    int t = threadIdx.x;
    int r0 = blockIdx.y * 5;
    int w = t >> 5, lane = t & 31;
    if (w < 5) {  // LN of row r0+w
        const float* row = x + (r0 + w) * D;
        float vbuf[7];
        float s = 0.f, sq = 0.f;
        #pragma unroll
        for (int i = 0; i < 7; i++) {
            int p = lane + i * 32;
            float v = (p < D) ? row[p] : 0.f;
            vbuf[i] = v; s += v; sq += v * v;
        }
        for (int o = 16; o > 0; o >>= 1) {
            s  += __shfl_xor_sync(0xffffffffu, s, o);
            sq += __shfl_xor_sync(0xffffffffu, sq, o);
        }
        float mean = s * (1.f / (float)D);
        float var  = sq * (1.f / (float)D) - mean * mean;
        float rstd = rsqrtf(var + 1e-5f);
        #pragma unroll
        for (int i = 0; i < 7; i++) {
            int p = lane + i * 32;
            if (p < D) hs[w * D + p] = (vbuf[i] - mean) * rstd * ln1g[p] + ln1b[p];
        }
    }
    __syncthreads();
    int kc = t >> 7, cl = t & 127;
    int col = blockIdx.x * 128 + cl;
    int ks = kc * 49;
    float a0 = 0.f, a1 = 0.f, a2 = 0.f, a3 = 0.f, a4 = 0.f;
    const float* wp = wq + ks * QKV3 + col;
    #pragma unroll 1
    for (int i = 0; i < 49; i += 7) {
        float wv[7];
        #pragma unroll
        for (int j = 0; j < 7; j++) wv[j] = wp[(i + j) * QKV3];
        #pragma unroll
        for (int j = 0; j < 7; j++) {
            int k = ks + i + j;
            float wj = wv[j];
            a0 += hs[0 * D + k] * wj;
            a1 += hs[1 * D + k] * wj;
            a2 += hs[2 * D + k] * wj;
            a3 += hs[3 * D + k] * wj;
            a4 += hs[4 * D + k] * wj;
        }
    }
    if (kc > 0) {
        float* sp = sred + (kc - 1) * 5 * 128 + cl;
        sp[0] = a0; sp[128] = a1; sp[256] = a2; sp[384] = a3; sp[512] = a4;
    }
    __syncthreads();
    if (kc == 0) {
        #pragma unroll
        for (int c = 0; c < 3; c++) {
            const float* sp = sred + c * 5 * 128 + cl;
            a0 += sp[0]; a1 += sp[128]; a2 += sp[256]; a3 += sp[384]; a4 += sp[512];
        }
        float* op = g_qkv + r0 * QKV3 + col;
        op[0] = a0; op[QKV3] = a1; op[2 * QKV3] = a2; op[3 * QKV3] = a3; op[4 * QKV3] = a4;
    }
}

// ================= attention: one block per (head, query) =================
__global__ void k_attn() {
    int h = blockIdx.x, i = blockIdx.y;
    int t = threadIdx.x;  // 128
    __shared__ float q[DH];
    __shared__ float p[SEQ];
    __shared__ float redm[4], reds[4];
    if (t < DH) q[t] = g_qkv[i * QKV3 + h * DH + t];
    __syncthreads();
    float sc = -1e30f;
    if (t < SEQ) {
        const float* kr = g_qkv + t * QKV3 + INNER + h * DH;
        float a0 = 0.f, a1 = 0.f, a2 = 0.f, a3 = 0.f;
        #pragma unroll
        for (int d = 0; d < DH; d += 4) {
            a0 += q[d + 0] * kr[d + 0];
            a1 += q[d + 1] * kr[d + 1];
            a2 += q[d + 2] * kr[d + 2];
            a3 += q[d + 3] * kr[d + 3];
        }
        sc = (a0 + a1 + a2 + a3) * 0.125f;
    }
    float m = sc;
    for (int o = 16; o > 0; o >>= 1) m = fmaxf(m, __shfl_xor_sync(0xffffffffu, m, o));
    if ((t & 31) == 0) redm[t >> 5] = m;
    __syncthreads();
    m = fmaxf(fmaxf(redm[0], redm[1]), fmaxf(redm[2], redm[3]));
    float e = (t < SEQ) ? expf(sc - m) : 0.f;
    float ssum = e;
    for (int o = 16; o > 0; o >>= 1) ssum += __shfl_xor_sync(0xffffffffu, ssum, o);
    if ((t & 31) == 0) reds[t >> 5] = ssum;
    __syncthreads();
    float inv = 1.f / (reds[0] + reds[1] + reds[2] + reds[3]);
    if (t < SEQ) p[t] = e * inv;
    __syncthreads();
    if (t < DH) {
        float acc = 0.f;
        #pragma unroll 1
        for (int j = 0; j < SEQ; j++)
            acc += p[j] * g_qkv[j * QKV3 + 2 * INNER + h * DH + t];
        g_o[i * INNER + h * DH + t] = acc;
    }
}

// ================= out-proj + residuals, K=512 split 4 ways =================
// grid (2, 13), 392 threads: kc = t/98, cl = t%98.
__global__ void k_proj(const float* __restrict__ wout, const float* __restrict__ bout,
                       const float* __restrict__ x) {
    __shared__ float os[5 * INNER];
    __shared__ float sred[3 * 5 * 98];
    int t = threadIdx.x;
    int r0 = blockIdx.y * 5;
    for (int i = t; i < 5 * INNER; i += 392) os[i] = g_o[r0 * INNER + i];
    __syncthreads();
    int kc = t / 98, cl = t - kc * 98;
    int col = blockIdx.x * 98 + cl;
    int ks = kc * 128;
    float a0 = 0.f, a1 = 0.f, a2 = 0.f, a3 = 0.f, a4 = 0.f;
    const float* wp = wout + ks * D + col;
    #pragma unroll 1
    for (int i = 0; i < 128; i += 8) {
        float wv[8];
        #pragma unroll
        for (int j = 0; j < 8; j++) wv[j] = wp[(i + j) * D];
        #pragma unroll
        for (int j = 0; j < 8; j++) {
            int k = ks + i + j;
            float wj = wv[j];
            a0 += os[0 * INNER + k] * wj;
            a1 += os[1 * INNER + k] * wj;
            a2 += os[2 * INNER + k] * wj;
            a3 += os[3 * INNER + k] * wj;
            a4 += os[4 * INNER + k] * wj;
        }
    }
    if (kc > 0) {
        float* sp = sred + (kc - 1) * 5 * 98 + cl;
        sp[0] = a0; sp[98] = a1; sp[196] = a2; sp[294] = a3; sp[392] = a4;
    }
    __syncthreads();
    if (kc == 0) {
        #pragma unroll
        for (int c = 0; c < 3; c++) {
            const float* sp = sred + c * 5 * 98 + cl;
            a0 += sp[0]; a1 += sp[98]; a2 += sp[196]; a3 += sp[294]; a4 += sp[392];
        }
        float b = bout[col];
        float acc[5] = {a0, a1, a2, a3, a4};
        #pragma unroll
        for (int r = 0; r < 5; r++) {
            int row = r0 + r;
            g_x1[row * D + col] = acc[r] + b + x[row * D + col] + g_xatt[row * D + col];
        }
    }
}

// ================= LN2 (in-block) + ff1 GEMM + GELU, K split 4 ways =================
// grid (7, 13), 448 threads: kc = t/112, cl = t%112.
__global__ void k_ff1(const float* __restrict__ ln2g, const float* __restrict__ ln2b,
                      const float* __restrict__ w1, const float* __restrict__ b1) {
    __shared__ float hs[5 * D];
    __shared__ float sred[3 * 5 * 112];
    int t = threadIdx.x;
    int r0 = blockIdx.y * 5;
    int w = t >> 5, lane = t & 31;
    if (w < 5) {
        const float* row = g_x1 + (r0 + w) * D;
        float vbuf[7];
        float s = 0.f, sq = 0.f;
        #pragma unroll
        for (int i = 0; i < 7; i++) {
            int p = lane + i * 32;
            float v = (p < D) ? row[p] : 0.f;
            vbuf[i] = v; s += v; sq += v * v;
        }
        for (int o = 16; o > 0; o >>= 1) {
            s  += __shfl_xor_sync(0xffffffffu, s, o);
            sq += __shfl_xor_sync(0xffffffffu, sq, o);
        }
        float mean = s * (1.f / (float)D);
        float var  = sq * (1.f / (float)D) - mean * mean;
        float rstd = rsqrtf(var + 1e-5f);
        #pragma unroll
        for (int i = 0; i < 7; i++) {
            int p = lane + i * 32;
            if (p < D) hs[w * D + p] = (vbuf[i] - mean) * rstd * ln2g[p] + ln2b[p];
        }
    }
    __syncthreads();
    int kc = t / 112, cl = t - kc * 112;
    int col = blockIdx.x * 112 + cl;
    int ks = kc * 49;
    float a0 = 0.f, a1 = 0.f, a2 = 0.f, a3 = 0.f, a4 = 0.f;
    const float* wp = w1 + ks * MLP + col;
    #pragma unroll 1
    for (int i = 0; i < 49; i += 7) {
        float wv[7];
        #pragma unroll
        for (int j = 0; j < 7; j++) wv[j] = wp[(i + j) * MLP];
        #pragma unroll
        for (int j = 0; j < 7; j++) {
            int k = ks + i + j;
            float wj = wv[j];
            a0 += hs[0 * D + k] * wj;
            a1 += hs[1 * D + k] * wj;
            a2 += hs[2 * D + k] * wj;
            a3 += hs[3 * D + k] * wj;
            a4 += hs[4 * D + k] * wj;
        }
    }
    if (kc > 0) {
        float* sp = sred + (kc - 1) * 5 * 112 + cl;
        sp[0] = a0; sp[112] = a1; sp[224] = a2; sp[336] = a3; sp[448] = a4;
    }
    __syncthreads();
    if (kc == 0) {
        #pragma unroll
        for (int c = 0; c < 3; c++) {
            const float* sp = sred + c * 5 * 112 + cl;
            a0 += sp[0]; a1 += sp[112]; a2 += sp[224]; a3 += sp[336]; a4 += sp[448];
        }
        float b = b1[col];
        float acc[5] = {a0, a1, a2, a3, a4};
        #pragma unroll
        for (int r = 0; r < 5; r++) {
            float a = acc[r] + b;
            g_gelu[(r0 + r) * MLP + col] = 0.5f * a * (1.f + erff(a * 0.70710678118654752f));
        }
    }
}

// ================= ff2 + residual -> out, K=784 split 4 ways =================
// grid (2, 13), 392 threads: kc = t/98, cl = t%98.
__global__ void k_ff2(const float* __restrict__ w2, const float* __restrict__ b2,
                      float* __restrict__ out) {
    __shared__ float gs[5 * MLP];
    __shared__ float sred[3 * 5 * 98];
    int t = threadIdx.x;
    int r0 = blockIdx.y * 5;
    for (int i = t; i < 5 * MLP; i += 392) gs[i] = g_gelu[r0 * MLP + i];
    __syncthreads();
    int kc = t / 98, cl = t - kc * 98;
    int col = blockIdx.x * 98 + cl;
    int ks = kc * 196;
    float a0 = 0.f, a1 = 0.f, a2 = 0.f, a3 = 0.f, a4 = 0.f;
    const float* wp = w2 + ks * D + col;
    #pragma unroll 1
    for (int i = 0; i < 196; i += 7) {
        float wv[7];
        #pragma unroll
        for (int j = 0; j < 7; j++) wv[j] = wp[(i + j) * D];
        #pragma unroll
        for (int j = 0; j < 7; j++) {
            int k = ks + i + j;
            float wj = wv[j];
            a0 += gs[0 * MLP + k] * wj;
            a1 += gs[1 * MLP + k] * wj;
            a2 += gs[2 * MLP + k] * wj;
            a3 += gs[3 * MLP + k] * wj;
            a4 += gs[4 * MLP + k] * wj;
        }
    }
    if (kc > 0) {
        float* sp = sred + (kc - 1) * 5 * 98 + cl;
        sp[0] = a0; sp[98] = a1; sp[196] = a2; sp[294] = a3; sp[392] = a4;
    }
    __syncthreads();
    if (kc == 0) {
        #pragma unroll
        for (int c = 0; c < 3; c++) {
            const float* sp = sred + c * 5 * 98 + cl;
            a0 += sp[0]; a1 += sp[98]; a2 += sp[196]; a3 += sp[294]; a4 += sp[392];
        }
        float b = b2[col];
        float acc[5] = {a0, a1, a2, a3, a4};
        #pragma unroll
        for (int r = 0; r < 5; r++) {
            int row = r0 + r;
            out[row * D + col] = acc[r] + b + g_x1[row * D + col];
        }
    }
}

extern "C" void kernel_launch(void* const* d_in, const int* in_sizes, int n_in,
                              void* d_out, int out_size) {
    const float* x      = (const float*)d_in[0];
    const float* tokens = (const float*)d_in[1];
    const float* x_pe   = (const float*)d_in[2];
    const float* conv_k = (const float*)d_in[3];
    const float* bn_g   = (const float*)d_in[4];
    const float* bn_b   = (const float*)d_in[5];
    const float* bn_rm  = (const float*)d_in[6];
    const float* bn_rv  = (const float*)d_in[7];
    const float* fc_w1  = (const float*)d_in[8];
    const float* fc_w2  = (const float*)d_in[9];
    const float* ln1_g  = (const float*)d_in[10];
    const float* ln1_b  = (const float*)d_in[11];
    const float* ln2_g  = (const float*)d_in[12];
    const float* ln2_b  = (const float*)d_in[13];
    const float* w_qkv  = (const float*)d_in[14];
    const float* w_out  = (const float*)d_in[15];
    const float* b_out  = (const float*)d_in[16];
    const float* ff_w1  = (const float*)d_in[17];
    const float* ff_b1  = (const float*)d_in[18];
    const float* ff_w2  = (const float*)d_in[19];
    const float* ff_b2  = (const float*)d_in[20];
    float* out = (float*)d_out;

    k_convgate<<<1, 1024>>>(x_pe, conv_k, bn_g, bn_b, bn_rm, bn_rv, tokens, fc_w1, fc_w2);
    k_qkv<<<dim3(12, 13), 512>>>(x, ln1_g, ln1_b, w_qkv);
    k_attn<<<dim3(H, SEQ), 128>>>();
    k_proj<<<dim3(2, 13), 392>>>(w_out, b_out, x);
    k_ff1<<<dim3(7, 13), 448>>>(ln2_g, ln2_b, ff_w1, ff_b1);
    k_ff2<<<dim3(2, 13), 392>>>(ff_w2, ff_b2, out);
}

// round 6
// speedup vs baseline: 4.7246x; 2.5619x over previous
#include <cuda_runtime.h>
#include <math.h>

#define D     196
#define NCH   64
#define H     8
#define DH    64
#define INNER 512
#define QKV3  1536
#define MLP   784
#define SEQ   65

// ---- scratch (no allocations allowed) ----
__device__ float g_xatt[SEQ * D];
__device__ float g_qkv[SEQ * QKV3];
__device__ float g_o[SEQ * INNER];
__device__ float g_x1[SEQ * D];
__device__ float g_gelu[SEQ * MLP];

// ================= LN1 + qkv GEMM (y<13) | conv+gate (y==13,x==0) =================
// GEMM blocks: 448 threads, 5 rows, C=64 cols, K split 7 ways. grid (24, 14).
__global__ void k_qkv(const float* __restrict__ x, const float* __restrict__ ln1g,
                      const float* __restrict__ ln1b, const float* __restrict__ wq,
                      const float* __restrict__ xpe, const float* __restrict__ ck,
                      const float* __restrict__ bng, const float* __restrict__ bnb,
                      const float* __restrict__ bnrm, const float* __restrict__ bnrv,
                      const float* __restrict__ tokens,
                      const float* __restrict__ fc1, const float* __restrict__ fc2) {
    __shared__ float hs[5 * D];
    __shared__ float sred[6 * 5 * 64];
    __shared__ float b1s[NCH], b2s[NCH], ts12[12], cs[NCH];
    __shared__ int middle_s;
    int t = threadIdx.x;           // 448
    int w = t >> 5, lane = t & 31; // 14 warps

    if (blockIdx.y == 13) {
        if (blockIdx.x != 0) return;
        // ---- conv+bn+relu mean, sort gate, FC, x_att ----
        float k0 = ck[3], k1 = ck[4], k2 = ck[5];
        float inv = rsqrtf(bnrv[0] + 1e-5f);
        float gg = bng[0], bb = bnb[0], rm = bnrm[0];
        for (int ch = w; ch < NCH; ch += 14) {
            const float* row = xpe + ch * D;
            float s = 0.f;
            for (int p = lane; p < D; p += 32) {
                float left  = (p > 0)     ? row[p - 1] : 0.f;
                float mid   = row[p];
                float right = (p < D - 1) ? row[p + 1] : 0.f;
                float conv  = k0 * left + k1 * mid + k2 * right;
                float bn    = (conv - rm) * inv * gg + bb;
                s += fmaxf(bn, 0.f);
            }
            for (int o = 16; o > 0; o >>= 1) s += __shfl_xor_sync(0xffffffffu, s, o);
            if (lane == 0) b1s[ch] = s * (1.f / (float)D);
        }
        __syncthreads();
        if (t == 0) {
            float mx = -1e30f, mn = 1e30f;
            int cnt_le = 0, any_pos = 0;
            for (int i = 0; i < NCH; i++) {
                float v = b1s[i];
                mx = fmaxf(mx, v); mn = fminf(mn, v);
                if (v <= 0.f) cnt_le++; else any_pos = 1;
            }
            int middle;
            if (mx < 0.f || mn > 0.f) middle = 32;
            else middle = any_pos ? cnt_le : 0;
            middle_s = middle;
        }
        __syncthreads();
        if (t < NCH) {
            float b1 = b1s[t];
            int rank = 0;
            for (int j = 0; j < NCH; j++) {
                float vj = b1s[j];
                if (vj < b1 || (vj == b1 && j < t)) rank++;
            }
            int middle = middle_s;
            float ls = (float)middle, le = (float)(NCH - middle);
            float b2;
            if (rank < middle) b2 = b1 - 1.f / (1.f + powf(ls, b1));
            else               b2 = b1 + 1.f / (1.f + powf(le, -b1));
            b2s[t] = b2;
        }
        __syncthreads();
        if (t < 12) {
            float acc = 0.f;
            for (int i = 0; i < NCH; i++) acc += b2s[i] * fc1[i * 12 + t];
            ts12[t] = fmaxf(acc, 0.f);
        }
        __syncthreads();
        if (t < NCH) {
            float acc = 0.f;
            for (int j = 0; j < 12; j++) acc += ts12[j] * fc2[j * NCH + t];
            cs[t] = 1.f / (1.f + expf(-acc));
        }
        __syncthreads();
        for (int idx = t; idx < NCH * D; idx += 448) {
            int ch = idx / D, p = idx - ch * D;
            const float* row = xpe + ch * D;
            float left  = (p > 0)     ? row[p - 1] : 0.f;
            float mid   = row[p];
            float right = (p < D - 1) ? row[p + 1] : 0.f;
            float conv  = k0 * left + k1 * mid + k2 * right;
            float bn    = (conv - rm) * inv * gg + bb;
            g_xatt[idx] = fmaxf(bn, 0.f) * cs[ch];
        }
        for (int s = t; s < D; s += 448) g_xatt[NCH * D + s] = tokens[s];
        return;
    }

    // ---- GEMM path ----
    int r0 = blockIdx.y * 5;
    if (w < 5) {  // LN of row r0+w
        const float* row = x + (r0 + w) * D;
        float vbuf[7];
        float s = 0.f, sq = 0.f;
        #pragma unroll
        for (int i = 0; i < 7; i++) {
            int p = lane + i * 32;
            float v = (p < D) ? row[p] : 0.f;
            vbuf[i] = v; s += v; sq += v * v;
        }
        for (int o = 16; o > 0; o >>= 1) {
            s  += __shfl_xor_sync(0xffffffffu, s, o);
            sq += __shfl_xor_sync(0xffffffffu, sq, o);
        }
        float mean = s * (1.f / (float)D);
        float var  = sq * (1.f / (float)D) - mean * mean;
        float rstd = rsqrtf(var + 1e-5f);
        #pragma unroll
        for (int i = 0; i < 7; i++) {
            int p = lane + i * 32;
            if (p < D) hs[w * D + p] = (vbuf[i] - mean) * rstd * ln1g[p] + ln1b[p];
        }
    }
    __syncthreads();
    int kc = t >> 6, cl = t & 63;         // kc 0..6
    int col = blockIdx.x * 64 + cl;       // < 1536
    int ks = kc * 28;
    float a0 = 0.f, a1 = 0.f, a2 = 0.f, a3 = 0.f, a4 = 0.f;
    const float* wp = wq + ks * QKV3 + col;
    #pragma unroll 1
    for (int i = 0; i < 28; i += 7) {
        float wv[7];
        #pragma unroll
        for (int j = 0; j < 7; j++) wv[j] = wp[(i + j) * QKV3];
        #pragma unroll
        for (int j = 0; j < 7; j++) {
            int k = ks + i + j;
            float wj = wv[j];
            a0 += hs[0 * D + k] * wj;
            a1 += hs[1 * D + k] * wj;
            a2 += hs[2 * D + k] * wj;
            a3 += hs[3 * D + k] * wj;
            a4 += hs[4 * D + k] * wj;
        }
    }
    if (kc > 0) {
        float* sp = sred + (kc - 1) * 320 + cl;
        sp[0] = a0; sp[64] = a1; sp[128] = a2; sp[192] = a3; sp[256] = a4;
    }
    __syncthreads();
    if (kc == 0) {
        #pragma unroll
        for (int c = 0; c < 6; c++) {
            const float* sp = sred + c * 320 + cl;
            a0 += sp[0]; a1 += sp[64]; a2 += sp[128]; a3 += sp[192]; a4 += sp[256];
        }
        float* op = g_qkv + r0 * QKV3 + col;
        op[0] = a0; op[QKV3] = a1; op[2 * QKV3] = a2; op[3 * QKV3] = a3; op[4 * QKV3] = a4;
    }
}

// ================= attention: one block per (head, query) =================
__global__ void k_attn() {
    int h = blockIdx.x, i = blockIdx.y;
    int t = threadIdx.x;  // 128
    __shared__ float q[DH];
    __shared__ float p[SEQ];
    __shared__ float redm[4], reds[4];
    if (t < DH) q[t] = g_qkv[i * QKV3 + h * DH + t];
    __syncthreads();
    float sc = -1e30f;
    if (t < SEQ) {
        const float4* kr = (const float4*)(g_qkv + t * QKV3 + INNER + h * DH);
        float a0 = 0.f, a1 = 0.f, a2 = 0.f, a3 = 0.f;
        #pragma unroll
        for (int d4 = 0; d4 < 16; d4++) {
            float4 kv = kr[d4];
            const float* qq = q + d4 * 4;
            a0 += qq[0] * kv.x; a1 += qq[1] * kv.y;
            a2 += qq[2] * kv.z; a3 += qq[3] * kv.w;
        }
        sc = (a0 + a1 + a2 + a3) * 0.125f;
    }
    float m = sc;
    for (int o = 16; o > 0; o >>= 1) m = fmaxf(m, __shfl_xor_sync(0xffffffffu, m, o));
    if ((t & 31) == 0) redm[t >> 5] = m;
    __syncthreads();
    m = fmaxf(fmaxf(redm[0], redm[1]), fmaxf(redm[2], redm[3]));
    float e = (t < SEQ) ? expf(sc - m) : 0.f;
    float ssum = e;
    for (int o = 16; o > 0; o >>= 1) ssum += __shfl_xor_sync(0xffffffffu, ssum, o);
    if ((t & 31) == 0) reds[t >> 5] = ssum;
    __syncthreads();
    float inv = 1.f / (reds[0] + reds[1] + reds[2] + reds[3]);
    if (t < SEQ) p[t] = e * inv;
    __syncthreads();
    if (t < DH) {
        const float* vp = g_qkv + 2 * INNER + h * DH + t;
        float acc = 0.f;
        #pragma unroll
        for (int j0 = 0; j0 < SEQ; j0 += 13) {
            float vv[13];
            #pragma unroll
            for (int j = 0; j < 13; j++) vv[j] = vp[(j0 + j) * QKV3];
            #pragma unroll
            for (int j = 0; j < 13; j++) acc += p[j0 + j] * vv[j];
        }
        g_o[i * INNER + h * DH + t] = acc;
    }
}

// ================= out-proj + residuals: 3 rows, C=28, S=16. grid (7,22) ============
__global__ void k_proj(const float* __restrict__ wout, const float* __restrict__ bout,
                       const float* __restrict__ x) {
    __shared__ float os[3 * INNER];
    __shared__ float sred[15 * 3 * 28];
    int t = threadIdx.x;  // 448
    int r0 = blockIdx.y * 3;
    for (int i = t; i < 3 * INNER; i += 448) {
        int row = r0 + (i >> 9);
        os[i] = (row < SEQ) ? g_o[row * INNER + (i & (INNER - 1))] : 0.f;
    }
    __syncthreads();
    int kc = t / 28, cl = t - kc * 28;   // kc 0..15
    int col = blockIdx.x * 28 + cl;      // < 196
    int ks = kc * 32;
    float a0 = 0.f, a1 = 0.f, a2 = 0.f;
    const float* wp = wout + ks * D + col;
    #pragma unroll 1
    for (int i = 0; i < 32; i += 8) {
        float wv[8];
        #pragma unroll
        for (int j = 0; j < 8; j++) wv[j] = wp[(i + j) * D];
        #pragma unroll
        for (int j = 0; j < 8; j++) {
            int k = ks + i + j;
            float wj = wv[j];
            a0 += os[k] * wj; a1 += os[INNER + k] * wj; a2 += os[2 * INNER + k] * wj;
        }
    }
    if (kc > 0) {
        float* sp = sred + (kc - 1) * 84 + cl;
        sp[0] = a0; sp[28] = a1; sp[56] = a2;
    }
    __syncthreads();
    if (kc == 0) {
        #pragma unroll
        for (int c = 0; c < 15; c++) {
            const float* sp = sred + c * 84 + cl;
            a0 += sp[0]; a1 += sp[28]; a2 += sp[56];
        }
        float b = bout[col];
        float acc[3] = {a0, a1, a2};
        #pragma unroll
        for (int r = 0; r < 3; r++) {
            int row = r0 + r;
            if (row < SEQ)
                g_x1[row * D + col] = acc[r] + b + x[row * D + col] + g_xatt[row * D + col];
        }
    }
}

// ================= LN2 + ff1 + GELU: 3 rows, C=56, S=7. grid (14,22) ================
__global__ void k_ff1(const float* __restrict__ ln2g, const float* __restrict__ ln2b,
                      const float* __restrict__ w1, const float* __restrict__ b1) {
    __shared__ float hs[3 * D];
    __shared__ float sred[6 * 3 * 56];
    int t = threadIdx.x;  // 392
    int r0 = blockIdx.y * 3;
    int w = t >> 5, lane = t & 31;
    if (w < 3 && r0 + w < SEQ) {
        const float* row = g_x1 + (r0 + w) * D;
        float vbuf[7];
        float s = 0.f, sq = 0.f;
        #pragma unroll
        for (int i = 0; i < 7; i++) {
            int p = lane + i * 32;
            float v = (p < D) ? row[p] : 0.f;
            vbuf[i] = v; s += v; sq += v * v;
        }
        for (int o = 16; o > 0; o >>= 1) {
            s  += __shfl_xor_sync(0xffffffffu, s, o);
            sq += __shfl_xor_sync(0xffffffffu, sq, o);
        }
        float mean = s * (1.f / (float)D);
        float var  = sq * (1.f / (float)D) - mean * mean;
        float rstd = rsqrtf(var + 1e-5f);
        #pragma unroll
        for (int i = 0; i < 7; i++) {
            int p = lane + i * 32;
            if (p < D) hs[w * D + p] = (vbuf[i] - mean) * rstd * ln2g[p] + ln2b[p];
        }
    }
    __syncthreads();
    int kc = t / 56, cl = t - kc * 56;  // kc 0..6
    int col = blockIdx.x * 56 + cl;     // < 784
    int ks = kc * 28;
    float a0 = 0.f, a1 = 0.f, a2 = 0.f;
    const float* wp = w1 + ks * MLP + col;
    #pragma unroll 1
    for (int i = 0; i < 28; i += 7) {
        float wv[7];
        #pragma unroll
        for (int j = 0; j < 7; j++) wv[j] = wp[(i + j) * MLP];
        #pragma unroll
        for (int j = 0; j < 7; j++) {
            int k = ks + i + j;
            float wj = wv[j];
            a0 += hs[k] * wj; a1 += hs[D + k] * wj; a2 += hs[2 * D + k] * wj;
        }
    }
    if (kc > 0) {
        float* sp = sred + (kc - 1) * 168 + cl;
        sp[0] = a0; sp[56] = a1; sp[112] = a2;
    }
    __syncthreads();
    if (kc == 0) {
        #pragma unroll
        for (int c = 0; c < 6; c++) {
            const float* sp = sred + c * 168 + cl;
            a0 += sp[0]; a1 += sp[56]; a2 += sp[112];
        }
        float b = b1[col];
        float acc[3] = {a0, a1, a2};
        #pragma unroll
        for (int r = 0; r < 3; r++) {
            int row = r0 + r;
            if (row < SEQ) {
                float a = acc[r] + b;
                g_gelu[row * MLP + col] = 0.5f * a * (1.f + erff(a * 0.70710678118654752f));
            }
        }
    }
}

// ================= ff2 + residual -> out: 3 rows, C=28, S=16. grid (7,22) ===========
__global__ void k_ff2(const float* __restrict__ w2, const float* __restrict__ b2,
                      float* __restrict__ out) {
    __shared__ float gs[3 * MLP];
    __shared__ float sred[15 * 3 * 28];
    int t = threadIdx.x;  // 448
    int r0 = blockIdx.y * 3;
    for (int i = t; i < 3 * MLP; i += 448) {
        int row = r0 + i / MLP;
        int k = i - (i / MLP) * MLP;
        gs[i] = (row < SEQ) ? g_gelu[row * MLP + k] : 0.f;
    }
    __syncthreads();
    int kc = t / 28, cl = t - kc * 28;  // kc 0..15
    int col = blockIdx.x * 28 + cl;     // < 196
    int ks = kc * 49;
    float a0 = 0.f, a1 = 0.f, a2 = 0.f;
    const float* wp = w2 + ks * D + col;
    #pragma unroll 1
    for (int i = 0; i < 49; i += 7) {
        float wv[7];
        #pragma unroll
        for (int j = 0; j < 7; j++) wv[j] = wp[(i + j) * D];
        #pragma unroll
        for (int j = 0; j < 7; j++) {
            int k = ks + i + j;
            float wj = wv[j];
            a0 += gs[k] * wj; a1 += gs[MLP + k] * wj; a2 += gs[2 * MLP + k] * wj;
        }
    }
    if (kc > 0) {
        float* sp = sred + (kc - 1) * 84 + cl;
        sp[0] = a0; sp[28] = a1; sp[56] = a2;
    }
    __syncthreads();
    if (kc == 0) {
        #pragma unroll
        for (int c = 0; c < 15; c++) {
            const float* sp = sred + c * 84 + cl;
            a0 += sp[0]; a1 += sp[28]; a2 += sp[56];
        }
        float b = b2[col];
        float acc[3] = {a0, a1, a2};
        #pragma unroll
        for (int r = 0; r < 3; r++) {
            int row = r0 + r;
            if (row < SEQ)
                out[row * D + col] = acc[r] + b + g_x1[row * D + col];
        }
    }
}

extern "C" void kernel_launch(void* const* d_in, const int* in_sizes, int n_in,
                              void* d_out, int out_size) {
    const float* x      = (const float*)d_in[0];
    const float* tokens = (const float*)d_in[1];
    const float* x_pe   = (const float*)d_in[2];
    const float* conv_k = (const float*)d_in[3];
    const float* bn_g   = (const float*)d_in[4];
    const float* bn_b   = (const float*)d_in[5];
    const float* bn_rm  = (const float*)d_in[6];
    const float* bn_rv  = (const float*)d_in[7];
    const float* fc_w1  = (const float*)d_in[8];
    const float* fc_w2  = (const float*)d_in[9];
    const float* ln1_g  = (const float*)d_in[10];
    const float* ln1_b  = (const float*)d_in[11];
    const float* ln2_g  = (const float*)d_in[12];
    const float* ln2_b  = (const float*)d_in[13];
    const float* w_qkv  = (const float*)d_in[14];
    const float* w_out  = (const float*)d_in[15];
    const float* b_out  = (const float*)d_in[16];
    const float* ff_w1  = (const float*)d_in[17];
    const float* ff_b1  = (const float*)d_in[18];
    const float* ff_w2  = (const float*)d_in[19];
    const float* ff_b2  = (const float*)d_in[20];
    float* out = (float*)d_out;

    k_qkv<<<dim3(24, 14), 448>>>(x, ln1_g, ln1_b, w_qkv,
                                 x_pe, conv_k, bn_g, bn_b, bn_rm, bn_rv,
                                 tokens, fc_w1, fc_w2);
    k_attn<<<dim3(H, SEQ), 128>>>();
    k_proj<<<dim3(7, 22), 448>>>(w_out, b_out, x);
    k_ff1<<<dim3(14, 22), 392>>>(ln2_g, ln2_b, ff_w1, ff_b1);
    k_ff2<<<dim3(7, 22), 448>>>(ff_w2, ff_b2, out);
}